// round 15
// baseline (speedup 1.0000x reference)
#include <cuda_runtime.h>
#include <cuda_fp16.h>
#include <cstdint>

#define NNODES 100000
#define EDGES  1600000
#define IN_F   165
#define HID    128
#define CHUNK0 66688   // 521 * 128  (~2/3 split: minimizes agg1/GEMM2 pipeline chain)

// Scratch (allocation-free rule: __device__ globals)
__device__ uint32_t g_bufG[(size_t)NNODES * 64];    // layer-1 GEMM out, packed half2 (k-pairs)
__device__ uint32_t g_bufG2[(size_t)NNODES * 64];   // layer-2 GEMM out, packed half2
__device__ uint32_t g_bufH[(size_t)NNODES * 64];    // layer-1 activation, packed half2
__device__ uint32_t g_W1h2[IN_F * 64];              // W1 fp16 (n-pairs)
__device__ uint32_t g_W2h2[HID * 64];               // W2 fp16
__device__ int      g_deg[NNODES];                  // self-restoring
__device__ float    g_dinv[NNODES];
__device__ int      g_rowptr[NNODES + 1];
__device__ int      g_csr_src[EDGES];
__device__ int      g_blockSums[128];

// ---------------- fp16 helpers ----------------

__device__ __forceinline__ uint32_t pack_f2(float a, float b) {
    __half2 t = __floats2half2_rn(a, b);
    return *(uint32_t*)&t;
}

__device__ __forceinline__ float4 unpack_h4(uint2 u) {
    float2 fa = __half22float2(*(__half2*)&u.x);
    float2 fb = __half22float2(*(__half2*)&u.y);
    return make_float4(fa.x, fa.y, fb.x, fb.y);
}

__device__ __forceinline__ void mma_f16(float* d, uint32_t a0, uint32_t a1,
                                        uint32_t a2, uint32_t a3,
                                        uint32_t b0, uint32_t b1) {
    asm volatile(
        "mma.sync.aligned.m16n8k16.row.col.f32.f16.f16.f32 "
        "{%0,%1,%2,%3}, {%4,%5,%6,%7}, {%8,%9}, {%0,%1,%2,%3};"
        : "+f"(d[0]), "+f"(d[1]), "+f"(d[2]), "+f"(d[3])
        : "r"(a0), "r"(a1), "r"(a2), "r"(a3), "r"(b0), "r"(b1));
}

// ---------------- W pre-convert (W1 and W2 in one launch) ----------------

__global__ void preconv_all_kernel(const float* __restrict__ W1,
                                   const float* __restrict__ W2,
                                   uint32_t* __restrict__ W1h2,
                                   uint32_t* __restrict__ W2h2) {
    const int n1 = IN_F * 64;
    const int n2 = HID * 64;
    int i = blockIdx.x * blockDim.x + threadIdx.x;
    if (i < n1) {
        W1h2[i] = pack_f2(W1[2 * i], W1[2 * i + 1]);
    } else if (i < n1 + n2) {
        int k = i - n1;
        W2h2[k] = pack_f2(W2[2 * k], W2[2 * k + 1]);
    }
}

// ---------------- degree ----------------

__global__ void deg_kernel(const int* __restrict__ dst, int* __restrict__ deg, int e) {
    int i = blockIdx.x * blockDim.x + threadIdx.x;
    if (i < e) atomicAdd(&deg[dst[i]], 1);
}

// ---------------- prefix scan of deg -> rowptr; also dinv --------------------------
// Two kernels: per-block sums, then final scan (each block redundantly scans the
// block sums itself — removes the middle single-block kernel).

__global__ __launch_bounds__(256)
void scan_block_sums(const int* __restrict__ deg, int* __restrict__ blockSums, int n) {
    __shared__ int sdata[256];
    int base = blockIdx.x * 2048;
    int tid = threadIdx.x;
    int s = 0;
#pragma unroll
    for (int j = 0; j < 8; j++) {
        int i = base + tid * 8 + j;
        if (i < n) s += deg[i];
    }
    sdata[tid] = s;
    __syncthreads();
    for (int off = 128; off; off >>= 1) {
        if (tid < off) sdata[tid] += sdata[tid + off];
        __syncthreads();
    }
    if (tid == 0) blockSums[blockIdx.x] = sdata[0];
}

__global__ __launch_bounds__(256)
void scan_final(const int* __restrict__ deg, const int* __restrict__ blockSums,
                int* __restrict__ rowptr, float* __restrict__ dinv, int n, int nb) {
    __shared__ int tsum[256];
    __shared__ int sOff[64];
    int base = blockIdx.x * 2048;
    int tid  = threadIdx.x;
    int lane = tid & 31;

    // warp 0: exclusive-scan blockSums (nb <= 64) into sOff
    if (tid < 32) {
        int v0 = (lane      < nb) ? blockSums[lane]      : 0;
        int v1 = (lane + 32 < nb) ? blockSums[lane + 32] : 0;
        int s0 = v0;
#pragma unroll
        for (int off = 1; off < 32; off <<= 1) {
            int t = __shfl_up_sync(0xFFFFFFFFu, s0, off);
            if (lane >= off) s0 += t;
        }
        int total0 = __shfl_sync(0xFFFFFFFFu, s0, 31);
        int s1 = v1;
#pragma unroll
        for (int off = 1; off < 32; off <<= 1) {
            int t = __shfl_up_sync(0xFFFFFFFFu, s1, off);
            if (lane >= off) s1 += t;
        }
        sOff[lane]      = s0 - v0;
        sOff[lane + 32] = total0 + s1 - v1;
    }

    int loc[8];
    int dv[8];
    int s = 0;
#pragma unroll
    for (int j = 0; j < 8; j++) {
        int i = base + tid * 8 + j;
        int v = (i < n) ? deg[i] : 0;
        dv[j]  = v;
        loc[j] = s;
        s += v;
    }
    tsum[tid] = s;
    __syncthreads();
    for (int off = 1; off < 256; off <<= 1) {
        int t = (tid >= off) ? tsum[tid - off] : 0;
        __syncthreads();
        tsum[tid] += t;
        __syncthreads();
    }
    int threadOff = tsum[tid] - s;  // exclusive within block
    int cOff = sOff[blockIdx.x];
#pragma unroll
    for (int j = 0; j < 8; j++) {
        int i = base + tid * 8 + j;
        if (i < n) {
            int rp = cOff + threadOff + loc[j];
            rowptr[i] = rp;
            dinv[i]   = rsqrtf((float)(dv[j] + 1));   // +1 self-loop
            if (i == n - 1) rowptr[n] = rp + dv[j];
        }
    }
}

// ---------------- scatter edges into CSR slots (counts deg back down to 0) ----------

__global__ void scatter_kernel(const int* __restrict__ src, const int* __restrict__ dst,
                               const int* __restrict__ rowptr, int* __restrict__ deg,
                               int* __restrict__ csr, int e) {
    int i = blockIdx.x * blockDim.x + threadIdx.x;
    if (i < e) {
        int d = dst[i];
        int pos = rowptr[d] + atomicAdd(&deg[d], -1) - 1;   // unique slot; deg ends at 0
        csr[pos] = src[i];
    }
}

// ---------------- GEMM (pure fp16 HMMA, fp32 accum): -------------------------------
// Gh2[r0..n1, 64] = packed-half2( A[r0..n1,K] @ W[K,128] )
// 128x128 tile, BK=16, 256 threads = 8 warps (2x4), warp tile 64x32 = 4x4 m16n8k16.
// PRE=true : A supplied as packed half2 (k-pairs)  [GEMM2: H]
// PRE=false: A is float, converted in-kernel       [GEMM1: x]

template <int K, bool PRE>
__global__ __launch_bounds__(256)
void gemm_kernel(const float* __restrict__ A,
                 const uint32_t* __restrict__ Ah2,
                 const uint32_t* __restrict__ Wh2,
                 uint32_t* __restrict__ Gh2, int row0, int n1) {
    constexpr int BM = 128, BK = 16;
    constexpr int LDK = 20;                      // half row stride (40B)
    constexpr int TILES = (K + BK - 1) / BK;

    __shared__ __align__(16) __half Ah[2][BM][LDK];
    __shared__ __align__(16) __half Bh[2][128][LDK];

    const int tid  = threadIdx.x;
    const int wid  = tid >> 5;
    const int lane = tid & 31;
    const int g    = lane >> 2;   // group 0..7
    const int tig  = lane & 3;    // thread-in-group 0..3
    const int wm   = wid & 1;     // 0..1 -> 64 rows each
    const int wn   = wid >> 1;    // 0..3 -> 32 cols each
    const int rowBase = row0 + blockIdx.x * BM;

    float acc[4][4][4];
#pragma unroll
    for (int mf = 0; mf < 4; mf++)
#pragma unroll
        for (int nf = 0; nf < 4; nf++)
#pragma unroll
            for (int q = 0; q < 4; q++) acc[mf][nf][q] = 0.f;

    auto loadAB = [&](int t, int buf) {
        const int k0 = t * BK;
        // ---- A tile: 1024 k-pairs, 4 per thread ----
        if (PRE) {
#pragma unroll
            for (int j = 0; j < 4; j++) {
                int q = tid + 256 * j;
                int r = q >> 3, kp = q & 7;
                int gr = rowBase + r;
                uint32_t vh = 0;
                if (gr < n1) vh = Ah2[(size_t)gr * 64 + (k0 >> 1) + kp];
                *(uint32_t*)&Ah[buf][r][2 * kp] = vh;
            }
        } else {
#pragma unroll
            for (int j = 0; j < 4; j++) {
                int q = tid + 256 * j;
                int r = q >> 3, kp = q & 7;
                int gr = rowBase + r;
                int gk = k0 + 2 * kp;
                float v0 = 0.f, v1 = 0.f;
                if (gr < n1) {
                    if (gk     < K) v0 = A[(size_t)gr * K + gk];
                    if (gk + 1 < K) v1 = A[(size_t)gr * K + gk + 1];
                }
                *(uint32_t*)&Ah[buf][r][2 * kp] = pack_f2(v0, v1);
            }
        }
        // ---- B tile from fp16 W: 1024 n-pairs, 4 per thread (transposed store) --
#pragma unroll
        for (int j = 0; j < 4; j++) {
            int l  = tid + 256 * j;
            int kk = l >> 6, np = l & 63;
            int gk = k0 + kk;
            uint32_t vh = 0;
            if (gk < K) vh = Wh2[gk * 64 + np];
            __half2 h2 = *(__half2*)&vh;
            Bh[buf][2 * np][kk]     = __low2half(h2);
            Bh[buf][2 * np + 1][kk] = __high2half(h2);
        }
    };

    loadAB(0, 0);
    __syncthreads();

    for (int t = 0; t < TILES; t++) {
        const int cur = t & 1;
        if (t + 1 < TILES) loadAB(t + 1, cur ^ 1);

        uint32_t bh[4][2];
#pragma unroll
        for (int nf = 0; nf < 4; nf++) {
            int c = wn * 32 + nf * 8 + g;
            bh[nf][0] = *(const uint32_t*)&Bh[cur][c][2 * tig];
            bh[nf][1] = *(const uint32_t*)&Bh[cur][c][2 * tig + 8];
        }
#pragma unroll
        for (int mf = 0; mf < 4; mf++) {
            int r  = wm * 64 + mf * 16 + g;
            uint32_t a0 = *(const uint32_t*)&Ah[cur][r][2 * tig];
            uint32_t a1 = *(const uint32_t*)&Ah[cur][r + 8][2 * tig];
            uint32_t a2 = *(const uint32_t*)&Ah[cur][r][2 * tig + 8];
            uint32_t a3 = *(const uint32_t*)&Ah[cur][r + 8][2 * tig + 8];
#pragma unroll
            for (int nf = 0; nf < 4; nf++)
                mma_f16(acc[mf][nf], a0, a1, a2, a3, bh[nf][0], bh[nf][1]);
        }
        __syncthreads();
    }

    // epilogue: pack adjacent-column pairs (c, c+1) to half2, single 4B store
#pragma unroll
    for (int mf = 0; mf < 4; mf++) {
        int r0 = rowBase + wm * 64 + mf * 16 + g;
        int r1 = r0 + 8;
#pragma unroll
        for (int nf = 0; nf < 4; nf++) {
            int c = wn * 32 + nf * 8 + 2 * tig;   // even
            if (r0 < n1)
                Gh2[(size_t)r0 * 64 + (c >> 1)] = pack_f2(acc[mf][nf][0], acc[mf][nf][1]);
            if (r1 < n1)
                Gh2[(size_t)r1 * 64 + (c >> 1)] = pack_f2(acc[mf][nf][2], acc[mf][nf][3]);
        }
    }
}

// ---------------- fused aggregation: warp per node in [n0,n1), CSR, no atomics --------
// Gather source g is packed half2 (4 halfs = uint2 per lane); accumulate fp32.
// EDGE_SCALE=true  (layer 1): acc = dinv[i]*g[i] + Σ dinv[s]*g[s];
//      h' = dinv[i]*relu(dinv[i]*acc + b), written as packed half2
// EDGE_SCALE=false (layer 2): acc = g[i] + Σ g[s]; h = relu(dinv[i]*acc + b)
// FINAL=true: classifier out = h @ Wc + bc (warp reduce)

template <bool EDGE_SCALE, bool FINAL>
__global__ __launch_bounds__(256)
void agg_fused_kernel(const uint2* __restrict__ g, const int* __restrict__ csr,
                      const int* __restrict__ rowptr,
                      const float* __restrict__ dinv, const float4* __restrict__ bias,
                      uint2* __restrict__ h,
                      const float4* __restrict__ Wc4, const float* __restrict__ bc,
                      float2* __restrict__ out, int n0, int n1) {
    int node = n0 + ((blockIdx.x * blockDim.x + threadIdx.x) >> 5);
    int lane = threadIdx.x & 31;
    if (node >= n1) return;

    const int start = rowptr[node];
    const int end   = rowptr[node + 1];
    const int cnt   = end - start;
    const float s   = dinv[node];

    float4 a[8];
    {   // self-loop term
        float4 v = unpack_h4(g[(size_t)node * 32 + lane]);
        if (EDGE_SCALE) { v.x *= s; v.y *= s; v.z *= s; v.w *= s; }
        a[0] = v;
    }
#pragma unroll
    for (int i = 1; i < 8; i++) a[i] = make_float4(0.f, 0.f, 0.f, 0.f);

    int j = 0;
    for (; j + 8 <= cnt; j += 8) {
        int idx[8];
#pragma unroll
        for (int u = 0; u < 8; u++) idx[u] = __ldg(&csr[start + j + u]);
        uint2 raw[8];
#pragma unroll
        for (int u = 0; u < 8; u++) raw[u] = g[(size_t)idx[u] * 32 + lane];
        float dv[8];
        if (EDGE_SCALE) {
#pragma unroll
            for (int u = 0; u < 8; u++) dv[u] = __ldg(&dinv[idx[u]]);
        }
#pragma unroll
        for (int u = 0; u < 8; u++) {
            float4 v = unpack_h4(raw[u]);
            if (EDGE_SCALE) {
                a[u].x = fmaf(dv[u], v.x, a[u].x);
                a[u].y = fmaf(dv[u], v.y, a[u].y);
                a[u].z = fmaf(dv[u], v.z, a[u].z);
                a[u].w = fmaf(dv[u], v.w, a[u].w);
            } else {
                a[u].x += v.x; a[u].y += v.y; a[u].z += v.z; a[u].w += v.w;
            }
        }
    }
    if (j + 4 <= cnt) {
        int idx[4];
#pragma unroll
        for (int u = 0; u < 4; u++) idx[u] = __ldg(&csr[start + j + u]);
        uint2 raw[4];
#pragma unroll
        for (int u = 0; u < 4; u++) raw[u] = g[(size_t)idx[u] * 32 + lane];
        float dv[4];
        if (EDGE_SCALE) {
#pragma unroll
            for (int u = 0; u < 4; u++) dv[u] = __ldg(&dinv[idx[u]]);
        }
#pragma unroll
        for (int u = 0; u < 4; u++) {
            float4 v = unpack_h4(raw[u]);
            if (EDGE_SCALE) {
                a[u].x = fmaf(dv[u], v.x, a[u].x);
                a[u].y = fmaf(dv[u], v.y, a[u].y);
                a[u].z = fmaf(dv[u], v.z, a[u].z);
                a[u].w = fmaf(dv[u], v.w, a[u].w);
            } else {
                a[u].x += v.x; a[u].y += v.y; a[u].z += v.z; a[u].w += v.w;
            }
        }
        j += 4;
    }
    for (; j < cnt; j++) {
        int s0 = __ldg(&csr[start + j]);
        float4 v = unpack_h4(g[(size_t)s0 * 32 + lane]);
        if (EDGE_SCALE) {
            float d0 = __ldg(&dinv[s0]);
            a[0].x = fmaf(d0, v.x, a[0].x);
            a[0].y = fmaf(d0, v.y, a[0].y);
            a[0].z = fmaf(d0, v.z, a[0].z);
            a[0].w = fmaf(d0, v.w, a[0].w);
        } else {
            a[0].x += v.x; a[0].y += v.y; a[0].z += v.z; a[0].w += v.w;
        }
    }

    float4 acc;
    acc.x = ((a[0].x + a[1].x) + (a[2].x + a[3].x)) + ((a[4].x + a[5].x) + (a[6].x + a[7].x));
    acc.y = ((a[0].y + a[1].y) + (a[2].y + a[3].y)) + ((a[4].y + a[5].y) + (a[6].y + a[7].y));
    acc.z = ((a[0].z + a[1].z) + (a[2].z + a[3].z)) + ((a[4].z + a[5].z) + (a[6].z + a[7].z));
    acc.w = ((a[0].w + a[1].w) + (a[2].w + a[3].w)) + ((a[4].w + a[5].w) + (a[6].w + a[7].w));

    float4 bv = bias[lane];
    float4 hv;
    hv.x = fmaxf(fmaf(s, acc.x, bv.x), 0.f);
    hv.y = fmaxf(fmaf(s, acc.y, bv.y), 0.f);
    hv.z = fmaxf(fmaf(s, acc.z, bv.z), 0.f);
    hv.w = fmaxf(fmaf(s, acc.w, bv.w), 0.f);

    if (!FINAL) {
        if (EDGE_SCALE) {   // pre-scale for next layer's source role
            hv.x *= s; hv.y *= s; hv.z *= s; hv.w *= s;
        }
        uint2 vh;
        vh.x = pack_f2(hv.x, hv.y);
        vh.y = pack_f2(hv.z, hv.w);
        h[(size_t)node * 32 + lane] = vh;
    } else {
        float4 w0 = __ldg(&Wc4[lane * 2]);
        float4 w1 = __ldg(&Wc4[lane * 2 + 1]);
        float p0 = hv.x * w0.x + hv.y * w0.z + hv.z * w1.x + hv.w * w1.z;
        float p1 = hv.x * w0.y + hv.y * w0.w + hv.z * w1.y + hv.w * w1.w;
#pragma unroll
        for (int off = 16; off; off >>= 1) {
            p0 += __shfl_xor_sync(0xFFFFFFFFu, p0, off);
            p1 += __shfl_xor_sync(0xFFFFFFFFu, p1, off);
        }
        if (lane == 0) out[node] = make_float2(p0 + bc[0], p1 + bc[1]);
    }
}

// ---------------- launch ----------------

extern "C" void kernel_launch(void* const* d_in, const int* in_sizes, int n_in,
                              void* d_out, int out_size) {
    const float* x  = (const float*)d_in[0];
    const int*   ei = (const int*)d_in[1];
    const float* W1 = (const float*)d_in[2];
    const float* b1 = (const float*)d_in[3];
    const float* W2 = (const float*)d_in[4];
    const float* b2 = (const float*)d_in[5];
    const float* Wc = (const float*)d_in[6];
    const float* bc = (const float*)d_in[7];
    float* out = (float*)d_out;

    const int n = NNODES;
    const int e = in_sizes[1] / 2;
    const int* src = ei;
    const int* dst = ei + e;

    float *DINV;
    uint32_t *G, *G2, *H, *W1H, *W2H;
    int *DEG, *ROWPTR, *CSR, *BSUMS;
    cudaGetSymbolAddress((void**)&G,      g_bufG);
    cudaGetSymbolAddress((void**)&G2,     g_bufG2);
    cudaGetSymbolAddress((void**)&H,      g_bufH);
    cudaGetSymbolAddress((void**)&W1H,    g_W1h2);
    cudaGetSymbolAddress((void**)&W2H,    g_W2h2);
    cudaGetSymbolAddress((void**)&DINV,   g_dinv);
    cudaGetSymbolAddress((void**)&DEG,    g_deg);
    cudaGetSymbolAddress((void**)&ROWPTR, g_rowptr);
    cudaGetSymbolAddress((void**)&CSR,    g_csr_src);
    cudaGetSymbolAddress((void**)&BSUMS,  g_blockSums);

    // side stream + events (host handles, created once)
    static cudaStream_t s_side = nullptr;
    static cudaEvent_t ev_fork = nullptr, ev_pre = nullptr, ev_a0 = nullptr, ev_a1 = nullptr;
    if (!s_side) {
        cudaStreamCreate(&s_side);
        cudaEventCreateWithFlags(&ev_fork, cudaEventDisableTiming);
        cudaEventCreateWithFlags(&ev_pre,  cudaEventDisableTiming);
        cudaEventCreateWithFlags(&ev_a0,   cudaEventDisableTiming);
        cudaEventCreateWithFlags(&ev_a1,   cudaEventDisableTiming);
    }

    const int c0 = CHUNK0;                       // chunk split (multiple of 128)
    const int gemmB_full = (n + 127) / 128;
    const int gemmB_c0   = c0 / 128;
    const int gemmB_c1   = (n - c0 + 127) / 128;
    const int aggB_full  = (int)(((long long)n * 32 + 255) / 256);
    const int aggB_c0    = (int)(((long long)c0 * 32 + 255) / 256);
    const int aggB_c1    = (int)(((long long)(n - c0) * 32 + 255) / 256);
    const int scanB      = (n + 2047) / 2048;
    const int preconvB   = ((IN_F + HID) * 64 + 255) / 256;

    // ---- fork: CSR build on side stream; W preconvert + GEMM1 on main ----
    cudaEventRecord(ev_fork, 0);
    cudaStreamWaitEvent(s_side, ev_fork, 0);

    deg_kernel<<<(e + 255) / 256, 256, 0, s_side>>>(dst, DEG, e);
    scan_block_sums<<<scanB, 256, 0, s_side>>>(DEG, BSUMS, n);
    scan_final<<<scanB, 256, 0, s_side>>>(DEG, BSUMS, ROWPTR, DINV, n, scanB);
    scatter_kernel<<<(e + 255) / 256, 256, 0, s_side>>>(src, dst, ROWPTR, DEG, CSR, e);
    cudaEventRecord(ev_pre, s_side);

    preconv_all_kernel<<<preconvB, 256>>>(W1, W2, W1H, W2H);
    gemm_kernel<IN_F, false><<<gemmB_full, 256>>>(x, nullptr, W1H, G, 0, n);

    // ---- join preprocessing, then pipelined agg1 / GEMM2 ----
    cudaStreamWaitEvent(0, ev_pre, 0);

    // agg1 chunk 0 on main (gathers G fp16, writes H[0,c0))
    agg_fused_kernel<true, false><<<aggB_c0, 256>>>((const uint2*)G, CSR, ROWPTR, DINV,
                                                    (const float4*)b1, (uint2*)H,
                                                    nullptr, nullptr, nullptr, 0, c0);
    cudaEventRecord(ev_a0, 0);

    // agg1 chunk 1 on side — concurrent with GEMM2 chunk 0
    cudaStreamWaitEvent(s_side, ev_a0, 0);
    agg_fused_kernel<true, false><<<aggB_c1, 256, 0, s_side>>>((const uint2*)G, CSR, ROWPTR, DINV,
                                                               (const float4*)b1, (uint2*)H,
                                                               nullptr, nullptr, nullptr, c0, n);
    cudaEventRecord(ev_a1, s_side);

    // GEMM2 chunk 0 on main: reads H[0,c0), writes G2[0,c0) (fp16 packed)
    gemm_kernel<HID, true><<<gemmB_c0, 256>>>(nullptr, H, W2H, G2, 0, c0);

    // GEMM2 chunk 1 after agg1(C1) completes
    cudaStreamWaitEvent(0, ev_a1, 0);
    gemm_kernel<HID, true><<<gemmB_c1, 256>>>(nullptr, H, W2H, G2, c0, n);

    // ---- layer 2 aggregation + fused classifier (gathers G2 fp16) ----
    agg_fused_kernel<false, true><<<aggB_full, 256>>>((const uint2*)G2, CSR, ROWPTR, DINV,
                                                      (const float4*)b2, nullptr,
                                                      (const float4*)Wc, bc, (float2*)out, 0, n);
}

// round 16
// speedup vs baseline: 1.4053x; 1.4053x over previous
#include <cuda_runtime.h>
#include <cuda_fp16.h>
#include <cstdint>

#define NNODES 100000
#define EDGES  1600000
#define IN_F   165
#define HID    128
#define CHUNK0 50048   // 391 * 128

// Scratch (allocation-free rule: __device__ globals)
__device__ uint32_t g_bufG[(size_t)NNODES * 64];    // layer-1 GEMM out, packed half2 (k-pairs)
__device__ uint32_t g_bufG2[(size_t)NNODES * 64];   // layer-2 GEMM out, packed half2
__device__ uint32_t g_bufH[(size_t)NNODES * 64];    // layer-1 activation, packed half2
__device__ uint32_t g_W1h2[IN_F * 64];              // W1 fp16 (n-pairs)
__device__ uint32_t g_W2h2[HID * 64];               // W2 fp16
__device__ int      g_deg[NNODES];                  // self-restoring
__device__ float    g_dinv[NNODES];
__device__ int      g_rowptr[NNODES + 1];
__device__ int      g_csr_src[EDGES];
__device__ int      g_blockSums[128];

// ---------------- fp16 helpers ----------------

__device__ __forceinline__ uint32_t pack_f2(float a, float b) {
    __half2 t = __floats2half2_rn(a, b);
    return *(uint32_t*)&t;
}

__device__ __forceinline__ float4 unpack_h4(uint2 u) {
    float2 fa = __half22float2(*(__half2*)&u.x);
    float2 fb = __half22float2(*(__half2*)&u.y);
    return make_float4(fa.x, fa.y, fb.x, fb.y);
}

__device__ __forceinline__ void mma_f16(float* d, uint32_t a0, uint32_t a1,
                                        uint32_t a2, uint32_t a3,
                                        uint32_t b0, uint32_t b1) {
    asm volatile(
        "mma.sync.aligned.m16n8k16.row.col.f32.f16.f16.f32 "
        "{%0,%1,%2,%3}, {%4,%5,%6,%7}, {%8,%9}, {%0,%1,%2,%3};"
        : "+f"(d[0]), "+f"(d[1]), "+f"(d[2]), "+f"(d[3])
        : "r"(a0), "r"(a1), "r"(a2), "r"(a3), "r"(b0), "r"(b1));
}

// ---------------- W pre-convert: float [K][128] -> packed half2 [K][64] --------

__global__ void preconv_kernel(const float* __restrict__ W,
                               uint32_t* __restrict__ Wh2, int n2) {
    int i = blockIdx.x * blockDim.x + threadIdx.x;
    if (i < n2) Wh2[i] = pack_f2(W[2 * i], W[2 * i + 1]);
}

// ---------------- degree ----------------

__global__ void deg_kernel(const int* __restrict__ dst, int* __restrict__ deg, int e) {
    int i = blockIdx.x * blockDim.x + threadIdx.x;
    if (i < e) atomicAdd(&deg[dst[i]], 1);
}

// ---------------- exclusive prefix scan of deg -> rowptr; also dinv ----------------

__global__ __launch_bounds__(256)
void scan_block_sums(const int* __restrict__ deg, int* __restrict__ blockSums, int n) {
    __shared__ int sdata[256];
    int base = blockIdx.x * 2048;
    int tid = threadIdx.x;
    int s = 0;
#pragma unroll
    for (int j = 0; j < 8; j++) {
        int i = base + tid * 8 + j;
        if (i < n) s += deg[i];
    }
    sdata[tid] = s;
    __syncthreads();
    for (int off = 128; off; off >>= 1) {
        if (tid < off) sdata[tid] += sdata[tid + off];
        __syncthreads();
    }
    if (tid == 0) blockSums[blockIdx.x] = sdata[0];
}

__global__ void scan_offsets(int* __restrict__ blockSums, int nb) {
    int lane = threadIdx.x;            // 32 threads
    int v0 = (lane      < nb) ? blockSums[lane]      : 0;
    int v1 = (lane + 32 < nb) ? blockSums[lane + 32] : 0;
    int s0 = v0;
#pragma unroll
    for (int off = 1; off < 32; off <<= 1) {
        int t = __shfl_up_sync(0xFFFFFFFFu, s0, off);
        if (lane >= off) s0 += t;
    }
    int total0 = __shfl_sync(0xFFFFFFFFu, s0, 31);
    int s1 = v1;
#pragma unroll
    for (int off = 1; off < 32; off <<= 1) {
        int t = __shfl_up_sync(0xFFFFFFFFu, s1, off);
        if (lane >= off) s1 += t;
    }
    if (lane      < nb) blockSums[lane]      = s0 - v0;            // exclusive
    if (lane + 32 < nb) blockSums[lane + 32] = total0 + s1 - v1;
}

__global__ __launch_bounds__(256)
void scan_final(const int* __restrict__ deg, const int* __restrict__ blockSums,
                int* __restrict__ rowptr, float* __restrict__ dinv, int n) {
    __shared__ int tsum[256];
    int base = blockIdx.x * 2048;
    int tid = threadIdx.x;
    int loc[8];
    int dv[8];
    int s = 0;
#pragma unroll
    for (int j = 0; j < 8; j++) {
        int i = base + tid * 8 + j;
        int v = (i < n) ? deg[i] : 0;
        dv[j]  = v;
        loc[j] = s;
        s += v;
    }
    tsum[tid] = s;
    __syncthreads();
    for (int off = 1; off < 256; off <<= 1) {
        int t = (tid >= off) ? tsum[tid - off] : 0;
        __syncthreads();
        tsum[tid] += t;
        __syncthreads();
    }
    int threadOff = tsum[tid] - s;  // exclusive within block
    int cOff = blockSums[blockIdx.x];
#pragma unroll
    for (int j = 0; j < 8; j++) {
        int i = base + tid * 8 + j;
        if (i < n) {
            int rp = cOff + threadOff + loc[j];
            rowptr[i] = rp;
            dinv[i]   = rsqrtf((float)(dv[j] + 1));   // +1 self-loop
            if (i == n - 1) rowptr[n] = rp + dv[j];
        }
    }
}

// ---------------- scatter edges into CSR slots (counts deg back down to 0) ----------

__global__ void scatter_kernel(const int* __restrict__ src, const int* __restrict__ dst,
                               const int* __restrict__ rowptr, int* __restrict__ deg,
                               int* __restrict__ csr, int e) {
    int i = blockIdx.x * blockDim.x + threadIdx.x;
    if (i < e) {
        int d = dst[i];
        int pos = rowptr[d] + atomicAdd(&deg[d], -1) - 1;   // unique slot; deg ends at 0
        csr[pos] = src[i];
    }
}

// ---------------- GEMM (pure fp16 HMMA, fp32 accum): -------------------------------
// Gh2[r0..n1, 64] = packed-half2( A[r0..n1,K] @ W[K,128] )
// 128x128 tile, BK=16, 256 threads = 8 warps (2x4), warp tile 64x32 = 4x4 m16n8k16.
// PRE=true : A supplied as packed half2 (k-pairs)  [GEMM2: H]
// PRE=false: A is float, converted in-kernel       [GEMM1: x]

template <int K, bool PRE>
__global__ __launch_bounds__(256)
void gemm_kernel(const float* __restrict__ A,
                 const uint32_t* __restrict__ Ah2,
                 const uint32_t* __restrict__ Wh2,
                 uint32_t* __restrict__ Gh2, int row0, int n1) {
    constexpr int BM = 128, BK = 16;
    constexpr int LDK = 20;                      // half row stride (40B)
    constexpr int TILES = (K + BK - 1) / BK;

    __shared__ __align__(16) __half Ah[2][BM][LDK];
    __shared__ __align__(16) __half Bh[2][128][LDK];

    const int tid  = threadIdx.x;
    const int wid  = tid >> 5;
    const int lane = tid & 31;
    const int g    = lane >> 2;   // group 0..7
    const int tig  = lane & 3;    // thread-in-group 0..3
    const int wm   = wid & 1;     // 0..1 -> 64 rows each
    const int wn   = wid >> 1;    // 0..3 -> 32 cols each
    const int rowBase = row0 + blockIdx.x * BM;

    float acc[4][4][4];
#pragma unroll
    for (int mf = 0; mf < 4; mf++)
#pragma unroll
        for (int nf = 0; nf < 4; nf++)
#pragma unroll
            for (int q = 0; q < 4; q++) acc[mf][nf][q] = 0.f;

    auto loadAB = [&](int t, int buf) {
        const int k0 = t * BK;
        // ---- A tile: 1024 k-pairs, 4 per thread ----
        if (PRE) {
#pragma unroll
            for (int j = 0; j < 4; j++) {
                int q = tid + 256 * j;
                int r = q >> 3, kp = q & 7;
                int gr = rowBase + r;
                uint32_t vh = 0;
                if (gr < n1) vh = Ah2[(size_t)gr * 64 + (k0 >> 1) + kp];
                *(uint32_t*)&Ah[buf][r][2 * kp] = vh;
            }
        } else {
#pragma unroll
            for (int j = 0; j < 4; j++) {
                int q = tid + 256 * j;
                int r = q >> 3, kp = q & 7;
                int gr = rowBase + r;
                int gk = k0 + 2 * kp;
                float v0 = 0.f, v1 = 0.f;
                if (gr < n1) {
                    if (gk     < K) v0 = A[(size_t)gr * K + gk];
                    if (gk + 1 < K) v1 = A[(size_t)gr * K + gk + 1];
                }
                *(uint32_t*)&Ah[buf][r][2 * kp] = pack_f2(v0, v1);
            }
        }
        // ---- B tile from fp16 W: 1024 n-pairs, 4 per thread (transposed store) --
#pragma unroll
        for (int j = 0; j < 4; j++) {
            int l  = tid + 256 * j;
            int kk = l >> 6, np = l & 63;
            int gk = k0 + kk;
            uint32_t vh = 0;
            if (gk < K) vh = Wh2[gk * 64 + np];
            __half2 h2 = *(__half2*)&vh;
            Bh[buf][2 * np][kk]     = __low2half(h2);
            Bh[buf][2 * np + 1][kk] = __high2half(h2);
        }
    };

    loadAB(0, 0);
    __syncthreads();

    for (int t = 0; t < TILES; t++) {
        const int cur = t & 1;
        if (t + 1 < TILES) loadAB(t + 1, cur ^ 1);

        uint32_t bh[4][2];
#pragma unroll
        for (int nf = 0; nf < 4; nf++) {
            int c = wn * 32 + nf * 8 + g;
            bh[nf][0] = *(const uint32_t*)&Bh[cur][c][2 * tig];
            bh[nf][1] = *(const uint32_t*)&Bh[cur][c][2 * tig + 8];
        }
#pragma unroll
        for (int mf = 0; mf < 4; mf++) {
            int r  = wm * 64 + mf * 16 + g;
            uint32_t a0 = *(const uint32_t*)&Ah[cur][r][2 * tig];
            uint32_t a1 = *(const uint32_t*)&Ah[cur][r + 8][2 * tig];
            uint32_t a2 = *(const uint32_t*)&Ah[cur][r][2 * tig + 8];
            uint32_t a3 = *(const uint32_t*)&Ah[cur][r + 8][2 * tig + 8];
#pragma unroll
            for (int nf = 0; nf < 4; nf++)
                mma_f16(acc[mf][nf], a0, a1, a2, a3, bh[nf][0], bh[nf][1]);
        }
        __syncthreads();
    }

    // epilogue: pack adjacent-column pairs (c, c+1) to half2, single 4B store
#pragma unroll
    for (int mf = 0; mf < 4; mf++) {
        int r0 = rowBase + wm * 64 + mf * 16 + g;
        int r1 = r0 + 8;
#pragma unroll
        for (int nf = 0; nf < 4; nf++) {
            int c = wn * 32 + nf * 8 + 2 * tig;   // even
            if (r0 < n1)
                Gh2[(size_t)r0 * 64 + (c >> 1)] = pack_f2(acc[mf][nf][0], acc[mf][nf][1]);
            if (r1 < n1)
                Gh2[(size_t)r1 * 64 + (c >> 1)] = pack_f2(acc[mf][nf][2], acc[mf][nf][3]);
        }
    }
}

// ---------------- fused aggregation: warp per node in [n0,n1), CSR, no atomics --------
// Gather source g is packed half2 (4 halfs = uint2 per lane); accumulate fp32.
// EDGE_SCALE=true  (layer 1): acc = dinv[i]*g[i] + Σ dinv[s]*g[s];
//      h' = dinv[i]*relu(dinv[i]*acc + b), written as packed half2
// EDGE_SCALE=false (layer 2): acc = g[i] + Σ g[s]; h = relu(dinv[i]*acc + b)
// FINAL=true: classifier out = h @ Wc + bc (warp reduce)

template <bool EDGE_SCALE, bool FINAL>
__global__ __launch_bounds__(256)
void agg_fused_kernel(const uint2* __restrict__ g, const int* __restrict__ csr,
                      const int* __restrict__ rowptr,
                      const float* __restrict__ dinv, const float4* __restrict__ bias,
                      uint2* __restrict__ h,
                      const float4* __restrict__ Wc4, const float* __restrict__ bc,
                      float2* __restrict__ out, int n0, int n1) {
    int node = n0 + ((blockIdx.x * blockDim.x + threadIdx.x) >> 5);
    int lane = threadIdx.x & 31;
    if (node >= n1) return;

    const int start = rowptr[node];
    const int end   = rowptr[node + 1];
    const int cnt   = end - start;
    const float s   = dinv[node];

    float4 a[8];
    {   // self-loop term
        float4 v = unpack_h4(g[(size_t)node * 32 + lane]);
        if (EDGE_SCALE) { v.x *= s; v.y *= s; v.z *= s; v.w *= s; }
        a[0] = v;
    }
#pragma unroll
    for (int i = 1; i < 8; i++) a[i] = make_float4(0.f, 0.f, 0.f, 0.f);

    int j = 0;
    for (; j + 8 <= cnt; j += 8) {
        int idx[8];
#pragma unroll
        for (int u = 0; u < 8; u++) idx[u] = __ldg(&csr[start + j + u]);
        uint2 raw[8];
#pragma unroll
        for (int u = 0; u < 8; u++) raw[u] = g[(size_t)idx[u] * 32 + lane];
        float dv[8];
        if (EDGE_SCALE) {
#pragma unroll
            for (int u = 0; u < 8; u++) dv[u] = __ldg(&dinv[idx[u]]);
        }
#pragma unroll
        for (int u = 0; u < 8; u++) {
            float4 v = unpack_h4(raw[u]);
            if (EDGE_SCALE) {
                a[u].x = fmaf(dv[u], v.x, a[u].x);
                a[u].y = fmaf(dv[u], v.y, a[u].y);
                a[u].z = fmaf(dv[u], v.z, a[u].z);
                a[u].w = fmaf(dv[u], v.w, a[u].w);
            } else {
                a[u].x += v.x; a[u].y += v.y; a[u].z += v.z; a[u].w += v.w;
            }
        }
    }
    if (j + 4 <= cnt) {
        int idx[4];
#pragma unroll
        for (int u = 0; u < 4; u++) idx[u] = __ldg(&csr[start + j + u]);
        uint2 raw[4];
#pragma unroll
        for (int u = 0; u < 4; u++) raw[u] = g[(size_t)idx[u] * 32 + lane];
        float dv[4];
        if (EDGE_SCALE) {
#pragma unroll
            for (int u = 0; u < 4; u++) dv[u] = __ldg(&dinv[idx[u]]);
        }
#pragma unroll
        for (int u = 0; u < 4; u++) {
            float4 v = unpack_h4(raw[u]);
            if (EDGE_SCALE) {
                a[u].x = fmaf(dv[u], v.x, a[u].x);
                a[u].y = fmaf(dv[u], v.y, a[u].y);
                a[u].z = fmaf(dv[u], v.z, a[u].z);
                a[u].w = fmaf(dv[u], v.w, a[u].w);
            } else {
                a[u].x += v.x; a[u].y += v.y; a[u].z += v.z; a[u].w += v.w;
            }
        }
        j += 4;
    }
    for (; j < cnt; j++) {
        int s0 = __ldg(&csr[start + j]);
        float4 v = unpack_h4(g[(size_t)s0 * 32 + lane]);
        if (EDGE_SCALE) {
            float d0 = __ldg(&dinv[s0]);
            a[0].x = fmaf(d0, v.x, a[0].x);
            a[0].y = fmaf(d0, v.y, a[0].y);
            a[0].z = fmaf(d0, v.z, a[0].z);
            a[0].w = fmaf(d0, v.w, a[0].w);
        } else {
            a[0].x += v.x; a[0].y += v.y; a[0].z += v.z; a[0].w += v.w;
        }
    }

    float4 acc;
    acc.x = ((a[0].x + a[1].x) + (a[2].x + a[3].x)) + ((a[4].x + a[5].x) + (a[6].x + a[7].x));
    acc.y = ((a[0].y + a[1].y) + (a[2].y + a[3].y)) + ((a[4].y + a[5].y) + (a[6].y + a[7].y));
    acc.z = ((a[0].z + a[1].z) + (a[2].z + a[3].z)) + ((a[4].z + a[5].z) + (a[6].z + a[7].z));
    acc.w = ((a[0].w + a[1].w) + (a[2].w + a[3].w)) + ((a[4].w + a[5].w) + (a[6].w + a[7].w));

    float4 bv = bias[lane];
    float4 hv;
    hv.x = fmaxf(fmaf(s, acc.x, bv.x), 0.f);
    hv.y = fmaxf(fmaf(s, acc.y, bv.y), 0.f);
    hv.z = fmaxf(fmaf(s, acc.z, bv.z), 0.f);
    hv.w = fmaxf(fmaf(s, acc.w, bv.w), 0.f);

    if (!FINAL) {
        if (EDGE_SCALE) {   // pre-scale for next layer's source role
            hv.x *= s; hv.y *= s; hv.z *= s; hv.w *= s;
        }
        uint2 vh;
        vh.x = pack_f2(hv.x, hv.y);
        vh.y = pack_f2(hv.z, hv.w);
        h[(size_t)node * 32 + lane] = vh;
    } else {
        float4 w0 = __ldg(&Wc4[lane * 2]);
        float4 w1 = __ldg(&Wc4[lane * 2 + 1]);
        float p0 = hv.x * w0.x + hv.y * w0.z + hv.z * w1.x + hv.w * w1.z;
        float p1 = hv.x * w0.y + hv.y * w0.w + hv.z * w1.y + hv.w * w1.w;
#pragma unroll
        for (int off = 16; off; off >>= 1) {
            p0 += __shfl_xor_sync(0xFFFFFFFFu, p0, off);
            p1 += __shfl_xor_sync(0xFFFFFFFFu, p1, off);
        }
        if (lane == 0) out[node] = make_float2(p0 + bc[0], p1 + bc[1]);
    }
}

// ---------------- launch ----------------

extern "C" void kernel_launch(void* const* d_in, const int* in_sizes, int n_in,
                              void* d_out, int out_size) {
    const float* x  = (const float*)d_in[0];
    const int*   ei = (const int*)d_in[1];
    const float* W1 = (const float*)d_in[2];
    const float* b1 = (const float*)d_in[3];
    const float* W2 = (const float*)d_in[4];
    const float* b2 = (const float*)d_in[5];
    const float* Wc = (const float*)d_in[6];
    const float* bc = (const float*)d_in[7];
    float* out = (float*)d_out;

    const int n = NNODES;
    const int e = in_sizes[1] / 2;
    const int* src = ei;
    const int* dst = ei + e;

    float *DINV;
    uint32_t *G, *G2, *H, *W1H, *W2H;
    int *DEG, *ROWPTR, *CSR, *BSUMS;
    cudaGetSymbolAddress((void**)&G,      g_bufG);
    cudaGetSymbolAddress((void**)&G2,     g_bufG2);
    cudaGetSymbolAddress((void**)&H,      g_bufH);
    cudaGetSymbolAddress((void**)&W1H,    g_W1h2);
    cudaGetSymbolAddress((void**)&W2H,    g_W2h2);
    cudaGetSymbolAddress((void**)&DINV,   g_dinv);
    cudaGetSymbolAddress((void**)&DEG,    g_deg);
    cudaGetSymbolAddress((void**)&ROWPTR, g_rowptr);
    cudaGetSymbolAddress((void**)&CSR,    g_csr_src);
    cudaGetSymbolAddress((void**)&BSUMS,  g_blockSums);

    // side stream + events (host handles, created once)
    static cudaStream_t s_side = nullptr;
    static cudaEvent_t ev_fork = nullptr, ev_pre = nullptr, ev_a0 = nullptr, ev_a1 = nullptr;
    if (!s_side) {
        cudaStreamCreate(&s_side);
        cudaEventCreateWithFlags(&ev_fork, cudaEventDisableTiming);
        cudaEventCreateWithFlags(&ev_pre,  cudaEventDisableTiming);
        cudaEventCreateWithFlags(&ev_a0,   cudaEventDisableTiming);
        cudaEventCreateWithFlags(&ev_a1,   cudaEventDisableTiming);
    }

    const int c0 = CHUNK0;                       // chunk split (multiple of 128)
    const int gemmB_full = (n + 127) / 128;
    const int gemmB_c0   = c0 / 128;
    const int gemmB_c1   = (n - c0 + 127) / 128;
    const int aggB_full  = (int)(((long long)n * 32 + 255) / 256);
    const int aggB_c0    = (int)(((long long)c0 * 32 + 255) / 256);
    const int aggB_c1    = (int)(((long long)(n - c0) * 32 + 255) / 256);
    const int scanB      = (n + 2047) / 2048;

    // ---- fork: CSR build + W2 convert on side stream; W1 convert + GEMM1 on main ----
    cudaEventRecord(ev_fork, 0);
    cudaStreamWaitEvent(s_side, ev_fork, 0);

    preconv_kernel<<<(HID * 64 + 255) / 256, 256, 0, s_side>>>(W2, W2H, HID * 64);
    deg_kernel<<<(e + 255) / 256, 256, 0, s_side>>>(dst, DEG, e);
    scan_block_sums<<<scanB, 256, 0, s_side>>>(DEG, BSUMS, n);
    scan_offsets<<<1, 32, 0, s_side>>>(BSUMS, scanB);
    scan_final<<<scanB, 256, 0, s_side>>>(DEG, BSUMS, ROWPTR, DINV, n);
    scatter_kernel<<<(e + 255) / 256, 256, 0, s_side>>>(src, dst, ROWPTR, DEG, CSR, e);
    cudaEventRecord(ev_pre, s_side);

    preconv_kernel<<<(IN_F * 64 + 255) / 256, 256>>>(W1, W1H, IN_F * 64);
    gemm_kernel<IN_F, false><<<gemmB_full, 256>>>(x, nullptr, W1H, G, 0, n);

    // ---- join preprocessing, then pipelined agg1 / GEMM2 ----
    cudaStreamWaitEvent(0, ev_pre, 0);

    // agg1 chunk 0 on main (gathers G fp16, writes H[0,c0))
    agg_fused_kernel<true, false><<<aggB_c0, 256>>>((const uint2*)G, CSR, ROWPTR, DINV,
                                                    (const float4*)b1, (uint2*)H,
                                                    nullptr, nullptr, nullptr, 0, c0);
    cudaEventRecord(ev_a0, 0);

    // agg1 chunk 1 on side — concurrent with GEMM2 chunk 0
    cudaStreamWaitEvent(s_side, ev_a0, 0);
    agg_fused_kernel<true, false><<<aggB_c1, 256, 0, s_side>>>((const uint2*)G, CSR, ROWPTR, DINV,
                                                               (const float4*)b1, (uint2*)H,
                                                               nullptr, nullptr, nullptr, c0, n);
    cudaEventRecord(ev_a1, s_side);

    // GEMM2 chunk 0 on main: reads H[0,c0), writes G2[0,c0) (fp16 packed)
    gemm_kernel<HID, true><<<gemmB_c0, 256>>>(nullptr, H, W2H, G2, 0, c0);

    // GEMM2 chunk 1 after agg1(C1) completes
    cudaStreamWaitEvent(0, ev_a1, 0);
    gemm_kernel<HID, true><<<gemmB_c1, 256>>>(nullptr, H, W2H, G2, c0, n);

    // ---- layer 2 aggregation + fused classifier (gathers G2 fp16) ----
    agg_fused_kernel<false, true><<<aggB_full, 256>>>((const uint2*)G2, CSR, ROWPTR, DINV,
                                                      (const float4*)b2, nullptr,
                                                      (const float4*)Wc, bc, (float2*)out, 0, n);
}